// round 12
// baseline (speedup 1.0000x reference)
#include <cuda_runtime.h>
#include <cuda_fp16.h>
#include <cstdint>

#define N_TOT  32768
#define DIM    64
#define KCODES 1024
#define BM     128
#define NTHR   256
#define NSLICE 4       // K-axis split: 4 blocks per M-tile
#define KSL    256     // codes per slice
#define NCHUNK 2       // chunks of 128 codes per slice
#define NCK    128

// output offsets (float32 elements), concatenated in reference return order
#define O_QV   0
#define O_IDX  2097152
#define O_LOSS 2129920
#define O_EMB  2129921     // ODD offset -> scalar stores only
#define O_CL   2195457
#define O_EMA  2196481     // ODD offset -> scalar stores only

typedef unsigned long long u64;
typedef unsigned int u32;

// ---- scratch (__device__ globals; no allocations allowed) ----
__device__ float g_dw[KCODES * DIM];
__device__ float g_ni[KCODES];
__device__ float g_ee[KCODES];
__device__ float g_loss;
__device__ uint4 g_esplit[2][KCODES * 8];   // 2 fp16 split terms, [1024 codes][128B rows]
__device__ u64   g_key[N_TOT];              // packed (dist,idx) argmin keys
__device__ int   g_cnt[N_TOT / BM];         // per-tile completion counters

// ---- smem layout (dynamic, ~100KB -> 2 blocks/SM) ----
#define A_OFF    0          // 2 x 16KB fp16 A tiles (SW128), z split
#define B_OFF    32768      // 2 x 32KB B double buffer (2 terms x 128 codes)
#define EE_OFF   98304      // 256 floats ||e||^2 slice
#define FLAG_OFF 99328      // int: last-block flag
#define SMEM_SZ  99584

#define SW128(b) ((b) ^ (((b) >> 3) & 0x70))

__device__ __forceinline__ u32 smem_u32(const void* p) {
    u32 a;
    asm("{ .reg .u64 t; cvta.to.shared.u64 t, %1; cvt.u32.u64 %0, t; }" : "=r"(a) : "l"(p));
    return a;
}
#define LDSM_X4(r, addr) \
    asm volatile("ldmatrix.sync.aligned.m8n8.x4.shared.b16 {%0,%1,%2,%3}, [%4];" \
        : "=r"((r)[0]), "=r"((r)[1]), "=r"((r)[2]), "=r"((r)[3]) : "r"(addr))
#define MMA_F16(c, a, b0, b1) \
    asm volatile("mma.sync.aligned.m16n8k16.row.col.f32.f16.f16.f32 " \
        "{%0,%1,%2,%3}, {%4,%5,%6,%7}, {%8,%9}, {%0,%1,%2,%3};" \
        : "+f"((c)[0]), "+f"((c)[1]), "+f"((c)[2]), "+f"((c)[3]) \
        : "r"((a)[0]), "r"((a)[1]), "r"((a)[2]), "r"((a)[3]), \
          "r"(b0), "r"(b1))
#define CP_ASYNC16(dst, src) \
    asm volatile("cp.async.cg.shared.global [%0], [%1], 16;" :: "r"(dst), "l"(src))
#define CP_COMMIT() asm volatile("cp.async.commit_group;" ::: "memory")
#define CP_WAIT(n)  asm volatile("cp.async.wait_group %0;" :: "n"(n) : "memory")

__device__ __forceinline__ void split2(float x, u32& h0, u32& h1) {
    __half a = __float2half_rn(x);
    float f0 = __half2float(a);
    __half b = __float2half_rn(x - f0);
    h0 = (u32)__half_as_ushort(a);
    h1 = (u32)__half_as_ushort(b);
}
__device__ __forceinline__ float hf_lo(u32 w) {
    return __half2float(__ushort_as_half((unsigned short)(w & 0xffffu)));
}
__device__ __forceinline__ float hf_hi(u32 w) {
    return __half2float(__ushort_as_half((unsigned short)(w >> 16)));
}
__device__ __forceinline__ u64 pack_key(float v, u32 k) {
    u32 u = __float_as_uint(v);
    u = (u & 0x80000000u) ? ~u : (u | 0x80000000u);
    return ((u64)u << 32) | (u64)k;
}

// ---------------------------------------------------------------------------
// Kernel 0: zero scratch, init g_key/g_cnt, ||e||^2, fp16-split embeddings
// ---------------------------------------------------------------------------
__global__ void k_prep(const float* __restrict__ emb) {
    int t = blockIdx.x * blockDim.x + threadIdx.x;   // 16384 threads
    reinterpret_cast<float4*>(g_dw)[t] = make_float4(0.f, 0.f, 0.f, 0.f);
    g_key[t]          = 0xFFFFFFFFFFFFFFFFULL;
    g_key[t + 16384]  = 0xFFFFFFFFFFFFFFFFULL;
    if (t < N_TOT / BM) g_cnt[t] = 0;
    {
        int code = t >> 4, dq = t & 15;
        float4 v = __ldg(reinterpret_cast<const float4*>(emb) + t);
        u32 h0[4], h1[4];
        split2(v.x, h0[0], h1[0]);
        split2(v.y, h0[1], h1[1]);
        split2(v.z, h0[2], h1[2]);
        split2(v.w, h0[3], h1[3]);
        u32 base = code * 32 + dq * 2;
        u32* p0 = reinterpret_cast<u32*>(g_esplit[0]);
        u32* p1 = reinterpret_cast<u32*>(g_esplit[1]);
        p0[base] = h0[0] | (h0[1] << 16);  p0[base + 1] = h0[2] | (h0[3] << 16);
        p1[base] = h1[0] | (h1[1] << 16);  p1[base + 1] = h1[2] | (h1[3] << 16);
    }
    if (t < KCODES) {
        g_ni[t] = 0.0f;
        const float4* e4 = reinterpret_cast<const float4*>(emb + (size_t)t * DIM);
        float s = 0.0f;
#pragma unroll
        for (int i = 0; i < 16; i++) {
            float4 v = e4[i];
            s += v.x * v.x + v.y * v.y + v.z * v.z + v.w * v.w;
        }
        g_ee[t] = s;
    }
    if (t == 0) g_loss = 0.0f;
}

// ---------------------------------------------------------------------------
// Kernel 1: HMMA distances, K-sliced 4-way. Block (t,s) handles 128 rows x
// 256 codes; cross-slice argmin via global atomicMin; last block per tile
// runs the fused epilogue.
// ---------------------------------------------------------------------------
__global__ __launch_bounds__(NTHR, 2)
void k_main(const float* __restrict__ z, const float* __restrict__ emb,
            float* __restrict__ out) {
    extern __shared__ __align__(16) unsigned char sm[];
    int*   sidx  = reinterpret_cast<int*>(sm + B_OFF);     // alias B (post-loop)
    float* lred  = reinterpret_cast<float*>(sm + B_OFF + 2048);
    float* ees   = reinterpret_cast<float*>(sm + EE_OFF);
    int*   flagp = reinterpret_cast<int*>(sm + FLAG_OFF);

    const u32 smb = smem_u32(sm);
    const int tid  = threadIdx.x;
    const int lane = tid & 31;
    const int wid  = tid >> 5;
    const int wrow = wid * 16;
    const int tile = blockIdx.x >> 2;       // M-tile
    const int ksl  = blockIdx.x & 3;        // K-slice
    const int row0 = tile * BM;
    const int kbase = ksl * KSL;

    // ---- stage ||e||^2 slice (256 floats)
    if (tid < KSL) ees[tid] = __ldg(&g_ee[kbase + tid]);

    // ---- prefetch chunk 0 B into buffer 0 (cp.async)
#pragma unroll
    for (int u = tid; u < 2048; u += NTHR) {
        int term = u >> 10;
        int rem  = u & 1023;
        int krow = rem >> 3;
        int seg  = rem & 7;
        const uint4* src = &g_esplit[term][(size_t)(kbase + krow) * 8 + seg];
        u32 dst = smb + B_OFF + term * 16384 + SW128((u32)(krow * 128 + seg * 16));
        CP_ASYNC16(dst, src);
    }
    CP_COMMIT();

    // ---- build 2 fp16 A tiles from z (identical across the 4 slices)
    for (int i = tid; i < BM * 16; i += NTHR) {
        int m = i >> 4, dq = i & 15;
        float4 v = *reinterpret_cast<const float4*>(z + (size_t)(row0 + m) * DIM + dq * 4);
        u32 h0[4], h1[4];
        split2(v.x, h0[0], h1[0]);
        split2(v.y, h0[1], h1[1]);
        split2(v.z, h0[2], h1[2]);
        split2(v.w, h0[3], h1[3]);
        u32 sw = SW128((u32)(m * 128 + dq * 8));
        u32* d0 = reinterpret_cast<u32*>(sm + A_OFF + sw);
        u32* d1 = reinterpret_cast<u32*>(sm + A_OFF + 16384 + sw);
        d0[0] = h0[0] | (h0[1] << 16);  d0[1] = h0[2] | (h0[3] << 16);
        d1[0] = h1[0] | (h1[1] << 16);  d1[1] = h1[2] | (h1[3] << 16);
    }
    __syncthreads();

    // ---- load A fragments into registers
    u32 afr[2][4][4];
    {
        int g = lane >> 3;
        int arow = wrow + (g & 1) * 8 + (lane & 7);
        int acol = (g >> 1) * 16;
#pragma unroll
        for (int t = 0; t < 2; t++)
#pragma unroll
            for (int kt = 0; kt < 4; kt++) {
                u32 addr = smb + A_OFF + t * 16384 +
                           SW128((u32)(arow * 128 + kt * 32 + acol));
                LDSM_X4(afr[t][kt], addr);
            }
    }

    float best0 = 3.4e38f, best1 = 3.4e38f;
    u32   idx0 = 0, idx1 = 0;

    const int brow    = lane & 7;
    const int bcolsel = ((lane >> 3) & 1) * 16;
    const int btile   = (lane >> 4) * 8;

    for (int c = 0; c < NCHUNK; c++) {
        const u32 bufc = smb + B_OFF + (u32)(c & 1) * 32768;

        __syncthreads();
        if (c < NCHUNK - 1) {
            int cn = c + 1;
            u32 bufn = smb + B_OFF + (u32)(cn & 1) * 32768;
#pragma unroll
            for (int u = tid; u < 2048; u += NTHR) {
                int term = u >> 10;
                int rem  = u & 1023;
                int krow = rem >> 3;
                int seg  = rem & 7;
                const uint4* src = &g_esplit[term][(size_t)(kbase + cn * NCK + krow) * 8 + seg];
                u32 dst = bufn + term * 16384 + SW128((u32)(krow * 128 + seg * 16));
                CP_ASYNC16(dst, src);
            }
            CP_COMMIT();
            CP_WAIT(1);
        } else {
            CP_WAIT(0);
        }
        __syncthreads();

        for (int p = 0; p < 8; p++) {        // n-tile pairs: tiles 2p, 2p+1
            float ccA0[4] = {0, 0, 0, 0}, ccA1[4] = {0, 0, 0, 0};
            float ccB0[4] = {0, 0, 0, 0}, ccB1[4] = {0, 0, 0, 0};
            int rbase = (p * 16 + btile + brow) * 128 + bcolsel;

#pragma unroll
            for (int h = 0; h < 2; h++) {
                u32 bb[2][2][4];
#pragma unroll
                for (int t = 0; t < 2; t++)
#pragma unroll
                    for (int q = 0; q < 2; q++) {
                        int kt = h * 2 + q;
                        u32 addr = bufc + t * 16384 + SW128((u32)(rbase + kt * 32));
                        LDSM_X4(bb[t][q], addr);
                    }
#pragma unroll
                for (int q = 0; q < 2; q++) {
                    int kt = h * 2 + q;
                    MMA_F16(ccA0, afr[0][kt], bb[1][q][0], bb[1][q][1]);
                    MMA_F16(ccB0, afr[0][kt], bb[1][q][2], bb[1][q][3]);
                    MMA_F16(ccA1, afr[1][kt], bb[0][q][0], bb[0][q][1]);
                    MMA_F16(ccB1, afr[1][kt], bb[0][q][2], bb[0][q][3]);
                    MMA_F16(ccA0, afr[0][kt], bb[0][q][0], bb[0][q][1]);
                    MMA_F16(ccB0, afr[0][kt], bb[0][q][2], bb[0][q][3]);
                }
            }

            int kl = c * NCK + p * 16 + 2 * (lane & 3);   // chunk-local code
            u32 kcA = (u32)(kbase + kl);
            u32 kcB = kcA + 8;
            float eA0 = ees[kl],     eA1 = ees[kl + 1];
            float eB0 = ees[kl + 8], eB1 = ees[kl + 9];
            {
                float d0 = fmaf(-2.0f, ccA0[0] + ccA1[0], eA0);
                float d1 = fmaf(-2.0f, ccA0[1] + ccA1[1], eA1);
                float cv = (d1 < d0) ? d1 : d0;
                u32   ck = (d1 < d0) ? kcA + 1 : kcA;
                if (cv < best0) { best0 = cv; idx0 = ck; }
                float d2 = fmaf(-2.0f, ccA0[2] + ccA1[2], eA0);
                float d3 = fmaf(-2.0f, ccA0[3] + ccA1[3], eA1);
                float cw = (d3 < d2) ? d3 : d2;
                u32   cx = (d3 < d2) ? kcA + 1 : kcA;
                if (cw < best1) { best1 = cw; idx1 = cx; }
            }
            {
                float d0 = fmaf(-2.0f, ccB0[0] + ccB1[0], eB0);
                float d1 = fmaf(-2.0f, ccB0[1] + ccB1[1], eB1);
                float cv = (d1 < d0) ? d1 : d0;
                u32   ck = (d1 < d0) ? kcB + 1 : kcB;
                if (cv < best0) { best0 = cv; idx0 = ck; }
                float d2 = fmaf(-2.0f, ccB0[2] + ccB1[2], eB0);
                float d3 = fmaf(-2.0f, ccB0[3] + ccB1[3], eB1);
                float cw = (d3 < d2) ? d3 : d2;
                u32   cx = (d3 < d2) ? kcB + 1 : kcB;
                if (cw < best1) { best1 = cw; idx1 = cx; }
            }
        }
    }

    // ---- reduce argmin across the 4 lanes sharing each row, publish globally
    u64 key0 = pack_key(best0, idx0);
    u64 key1 = pack_key(best1, idx1);
#pragma unroll
    for (int o = 1; o <= 2; o <<= 1) {
        u64 t0 = __shfl_xor_sync(0xFFFFFFFFu, key0, o);
        u64 t1 = __shfl_xor_sync(0xFFFFFFFFu, key1, o);
        if (t0 < key0) key0 = t0;
        if (t1 < key1) key1 = t1;
    }
    if ((lane & 3) == 0) {
        int r0 = wrow + (lane >> 2);
        atomicMin(&g_key[row0 + r0],     key0);
        atomicMin(&g_key[row0 + r0 + 8], key1);
    }
    __threadfence();        // release: atomicMins visible before counter bump
    __syncthreads();
    if (tid == 0) {
        int old = atomicAdd(&g_cnt[tile], 1);
        *flagp = (old == NSLICE - 1) ? 1 : 0;
    }
    __syncthreads();
    if (*flagp == 0) return;     // not the last slice -> done

    // ================= last block of this tile: fused epilogue ==============
    __threadfence();        // acquire: see all slices' atomicMins

    if (tid < BM) {
        u64 k;
        asm volatile("ld.global.cg.u64 %0, [%1];" : "=l"(k) : "l"(&g_key[row0 + tid]));
        int idx = (int)(k & 0xFFFFFFFFull);
        sidx[tid] = idx;
        out[O_IDX + row0 + tid] = (float)idx;
        atomicAdd(&g_ni[idx], 1.0f);
    }
    __syncthreads();

    float lacc = 0.0f;
    for (int i = tid; i < BM * 32; i += NTHR) {   // (d-pair, m): m fast
        int d2 = i >> 7;
        int m  = i & 127;
        u32 sw = SW128((u32)(m * 128 + d2 * 4));
        u32 w0 = *reinterpret_cast<u32*>(sm + A_OFF + sw);
        u32 w1 = *reinterpret_cast<u32*>(sm + A_OFF + 16384 + sw);
        float zlo = hf_lo(w0) + hf_lo(w1);
        float zhi = hf_hi(w0) + hf_hi(w1);
        int idx = sidx[m];
        int d = d2 * 2;
        float2 q = __ldg(reinterpret_cast<const float2*>(emb + (size_t)idx * DIM + d));
        float dlo = q.x - zlo, dhi = q.y - zhi;
        lacc += dlo * dlo + dhi * dhi;
        int row = row0 + m;
        int b = row >> 10, hw = row & 1023;
        size_t obase = ((size_t)(b * DIM + d) << 10) + hw;
        out[O_QV + obase]        = zlo + dlo;
        out[O_QV + obase + 1024] = zhi + dhi;
        atomicAdd(&g_dw[idx * DIM + d],     zlo);
        atomicAdd(&g_dw[idx * DIM + d + 1], zhi);
    }
#pragma unroll
    for (int o = 16; o > 0; o >>= 1) lacc += __shfl_xor_sync(0xFFFFFFFFu, lacc, o);
    if (lane == 0) lred[wid] = lacc;
    __syncthreads();
    if (tid == 0) {
        float s = 0.0f;
#pragma unroll
        for (int w = 0; w < NTHR / 32; w++) s += lred[w];
        atomicAdd(&g_loss, s);
    }
}

// ---------------------------------------------------------------------------
// Kernel 2: smoothing + EMA + new embeddings
// ---------------------------------------------------------------------------
__global__ __launch_bounds__(256)
void k_final(const float* __restrict__ cs, const float* __restrict__ ema,
             float* __restrict__ out) {
    __shared__ float red[8];
    const int tid = threadIdx.x;

    float part = 0.0f;
#pragma unroll
    for (int k = tid; k < KCODES; k += 256)
        part += cs[k] * 0.99f + g_ni[k] * 0.01f;
#pragma unroll
    for (int o = 16; o > 0; o >>= 1) part += __shfl_xor_sync(0xFFFFFFFFu, part, o);
    if ((tid & 31) == 0) red[tid >> 5] = part;
    __syncthreads();
    float n = 0.0f;
#pragma unroll
    for (int w = 0; w < 8; w++) n += red[w];

    if (blockIdx.x == 0 && tid == 0)
        out[O_LOSS] = 0.25f * g_loss / 2097152.0f;

    const int i0 = (blockIdx.x * 256 + tid) * 4;
    const int k  = i0 >> 6;
    float raw = cs[k] * 0.99f + g_ni[k] * 0.01f;
    float smooth = (raw + 1e-5f) / (n + 1024.0f * 1e-5f) * n;
    if ((i0 & 63) == 0) out[O_CL + k] = smooth;

    float4 ev = *reinterpret_cast<const float4*>(ema + i0);
    float4 dv = *reinterpret_cast<const float4*>(g_dw + i0);
    float inv = 1.0f / smooth;
    float ne0 = ev.x * 0.99f + dv.x * 0.01f;
    float ne1 = ev.y * 0.99f + dv.y * 0.01f;
    float ne2 = ev.z * 0.99f + dv.z * 0.01f;
    float ne3 = ev.w * 0.99f + dv.w * 0.01f;
    out[O_EMA + i0 + 0] = ne0;  out[O_EMB + i0 + 0] = ne0 * inv;
    out[O_EMA + i0 + 1] = ne1;  out[O_EMB + i0 + 1] = ne1 * inv;
    out[O_EMA + i0 + 2] = ne2;  out[O_EMB + i0 + 2] = ne2 * inv;
    out[O_EMA + i0 + 3] = ne3;  out[O_EMB + i0 + 3] = ne3 * inv;
}

// ---------------------------------------------------------------------------
extern "C" void kernel_launch(void* const* d_in, const int* in_sizes, int n_in,
                              void* d_out, int out_size) {
    const float* z   = (const float*)d_in[0];
    const float* emb = (const float*)d_in[1];
    const float* cs  = (const float*)d_in[2];
    const float* ema = (const float*)d_in[3];
    float* out = (float*)d_out;

    static bool attr_set = false;
    if (!attr_set) {
        cudaFuncSetAttribute(k_main, cudaFuncAttributeMaxDynamicSharedMemorySize, SMEM_SZ);
        attr_set = true;
    }

    k_prep<<<64, 256>>>(emb);
    k_main<<<(N_TOT / BM) * NSLICE, NTHR, SMEM_SZ>>>(z, emb, out);
    k_final<<<64, 256>>>(cs, ema, out);
}

// round 13
// speedup vs baseline: 1.0359x; 1.0359x over previous
#include <cuda_runtime.h>
#include <cuda_fp16.h>
#include <cstdint>

#define N_TOT  32768
#define DIM    64
#define KCODES 1024
#define BM     128
#define NTHR   256
#define NSLICE 4       // K-axis split: 4 blocks per M-tile
#define KSL    256     // codes per slice
#define NCHUNK 2       // chunks of 128 codes per slice
#define NCK    128

// output offsets (float32 elements), concatenated in reference return order
#define O_QV   0
#define O_IDX  2097152
#define O_LOSS 2129920
#define O_EMB  2129921     // ODD offset -> scalar stores only
#define O_CL   2195457
#define O_EMA  2196481     // ODD offset -> scalar stores only

typedef unsigned long long u64;
typedef unsigned int u32;

// ---- scratch (__device__ globals; no allocations allowed) ----
__device__ float g_dw[KCODES * DIM];
__device__ float g_ni[KCODES];
__device__ float g_ee[KCODES];
__device__ float g_loss;
__device__ uint4 g_esplit[2][KCODES * 8];   // fp16-split embeddings, 128B/row
__device__ uint4 g_zsplit[2][N_TOT * 8];    // fp16-split z, 128B/row (8MB)
__device__ u64   g_key[N_TOT];              // packed (dist,idx) argmin keys
__device__ int   g_cnt[N_TOT / BM];         // per-tile completion counters

// ---- smem layout (dynamic, ~100KB -> 2 blocks/SM) ----
#define A_OFF    0          // 2 x 16KB fp16 A tiles (SW128)
#define B_OFF    32768      // 2 x 32KB B double buffer
#define EE_OFF   98304      // 256 floats ||e||^2 slice
#define FLAG_OFF 99328
#define SMEM_SZ  99584

#define SW128(b) ((b) ^ (((b) >> 3) & 0x70))

__device__ __forceinline__ u32 smem_u32(const void* p) {
    u32 a;
    asm("{ .reg .u64 t; cvta.to.shared.u64 t, %1; cvt.u32.u64 %0, t; }" : "=r"(a) : "l"(p));
    return a;
}
#define LDSM_X4(r, addr) \
    asm volatile("ldmatrix.sync.aligned.m8n8.x4.shared.b16 {%0,%1,%2,%3}, [%4];" \
        : "=r"((r)[0]), "=r"((r)[1]), "=r"((r)[2]), "=r"((r)[3]) : "r"(addr))
#define MMA_F16(c, a, b0, b1) \
    asm volatile("mma.sync.aligned.m16n8k16.row.col.f32.f16.f16.f32 " \
        "{%0,%1,%2,%3}, {%4,%5,%6,%7}, {%8,%9}, {%0,%1,%2,%3};" \
        : "+f"((c)[0]), "+f"((c)[1]), "+f"((c)[2]), "+f"((c)[3]) \
        : "r"((a)[0]), "r"((a)[1]), "r"((a)[2]), "r"((a)[3]), \
          "r"(b0), "r"(b1))
#define CP_ASYNC16(dst, src) \
    asm volatile("cp.async.cg.shared.global [%0], [%1], 16;" :: "r"(dst), "l"(src))
#define CP_COMMIT() asm volatile("cp.async.commit_group;" ::: "memory")
#define CP_WAIT(n)  asm volatile("cp.async.wait_group %0;" :: "n"(n) : "memory")

__device__ __forceinline__ void split2(float x, u32& h0, u32& h1) {
    __half a = __float2half_rn(x);
    float f0 = __half2float(a);
    __half b = __float2half_rn(x - f0);
    h0 = (u32)__half_as_ushort(a);
    h1 = (u32)__half_as_ushort(b);
}
__device__ __forceinline__ float hf_lo(u32 w) {
    return __half2float(__ushort_as_half((unsigned short)(w & 0xffffu)));
}
__device__ __forceinline__ float hf_hi(u32 w) {
    return __half2float(__ushort_as_half((unsigned short)(w >> 16)));
}
__device__ __forceinline__ u64 pack_key(float v, u32 k) {
    u32 u = __float_as_uint(v);
    u = (u & 0x80000000u) ? ~u : (u | 0x80000000u);
    return ((u64)u << 32) | (u64)k;
}

// ---------------------------------------------------------------------------
// Kernel 0 (widened: 128 blocks x 256): zero scratch, init keys/counters,
// ||e||^2, fp16-split embeddings AND z into global arrays.
// ---------------------------------------------------------------------------
__global__ void k_prep(const float* __restrict__ emb, const float* __restrict__ z) {
    int t = blockIdx.x * blockDim.x + threadIdx.x;   // 0..32767
    if (t < 16384)
        reinterpret_cast<float4*>(g_dw)[t] = make_float4(0.f, 0.f, 0.f, 0.f);
    g_key[t] = 0xFFFFFFFFFFFFFFFFULL;
    if (t < N_TOT / BM) g_cnt[t] = 0;

    // ---- split embeddings (16384 float4 items)
    if (t < 16384) {
        int code = t >> 4, dq = t & 15;
        float4 v = __ldg(reinterpret_cast<const float4*>(emb) + t);
        u32 h0[4], h1[4];
        split2(v.x, h0[0], h1[0]);
        split2(v.y, h0[1], h1[1]);
        split2(v.z, h0[2], h1[2]);
        split2(v.w, h0[3], h1[3]);
        u32 base = code * 32 + dq * 2;
        u32* p0 = reinterpret_cast<u32*>(g_esplit[0]);
        u32* p1 = reinterpret_cast<u32*>(g_esplit[1]);
        p0[base] = h0[0] | (h0[1] << 16);  p0[base + 1] = h0[2] | (h0[3] << 16);
        p1[base] = h1[0] | (h1[1] << 16);  p1[base + 1] = h1[2] | (h1[3] << 16);
    }

    // ---- split z (524288 float4 items, 16 per thread, coalesced)
    {
        uint2* q0 = reinterpret_cast<uint2*>(g_zsplit[0]);
        uint2* q1 = reinterpret_cast<uint2*>(g_zsplit[1]);
#pragma unroll
        for (int k = 0; k < 16; k++) {
            int i = t + k * 32768;
            float4 v = __ldg(reinterpret_cast<const float4*>(z) + i);
            u32 h0[4], h1[4];
            split2(v.x, h0[0], h1[0]);
            split2(v.y, h0[1], h1[1]);
            split2(v.z, h0[2], h1[2]);
            split2(v.w, h0[3], h1[3]);
            // uint2 index = row*16 + dq  (row = i>>4, dq = i&15) = i
            q0[i] = make_uint2(h0[0] | (h0[1] << 16), h0[2] | (h0[3] << 16));
            q1[i] = make_uint2(h1[0] | (h1[1] << 16), h1[2] | (h1[3] << 16));
        }
    }

    if (t < KCODES) {
        g_ni[t] = 0.0f;
        const float4* e4 = reinterpret_cast<const float4*>(emb + (size_t)t * DIM);
        float s = 0.0f;
#pragma unroll
        for (int i = 0; i < 16; i++) {
            float4 v = e4[i];
            s += v.x * v.x + v.y * v.y + v.z * v.z + v.w * v.w;
        }
        g_ee[t] = s;
    }
    if (t == 0) g_loss = 0.0f;
}

// ---------------------------------------------------------------------------
// Kernel 1: HMMA distances, K-sliced 4-way, cp.async A AND B tiles (cheap
// prologue). Cross-slice argmin via global atomicMin; last block per tile
// runs the fused epilogue.
// ---------------------------------------------------------------------------
__global__ __launch_bounds__(NTHR, 2)
void k_main(const float* __restrict__ emb, float* __restrict__ out) {
    extern __shared__ __align__(16) unsigned char sm[];
    int*   sidx  = reinterpret_cast<int*>(sm + B_OFF);     // alias B (post-loop)
    float* lred  = reinterpret_cast<float*>(sm + B_OFF + 2048);
    float* ees   = reinterpret_cast<float*>(sm + EE_OFF);
    int*   flagp = reinterpret_cast<int*>(sm + FLAG_OFF);

    const u32 smb = smem_u32(sm);
    const int tid  = threadIdx.x;
    const int lane = tid & 31;
    const int wid  = tid >> 5;
    const int wrow = wid * 16;
    const int tile = blockIdx.x >> 2;
    const int ksl  = blockIdx.x & 3;
    const int row0 = tile * BM;
    const int kbase = ksl * KSL;

    // ---- prologue: cp.async A tiles (2048 x 16B) + B chunk0 (2048 x 16B)
#pragma unroll
    for (int u = tid; u < 2048; u += NTHR) {
        int term = u >> 10;
        int rem  = u & 1023;
        int m    = rem >> 3;
        int seg  = rem & 7;
        const uint4* srcA = &g_zsplit[term][(size_t)(row0 + m) * 8 + seg];
        u32 dstA = smb + A_OFF + term * 16384 + SW128((u32)(m * 128 + seg * 16));
        CP_ASYNC16(dstA, srcA);
        const uint4* srcB = &g_esplit[term][(size_t)(kbase + m) * 8 + seg];
        u32 dstB = smb + B_OFF + term * 16384 + SW128((u32)(m * 128 + seg * 16));
        CP_ASYNC16(dstB, srcB);
    }
    CP_COMMIT();

    if (tid < KSL) ees[tid] = __ldg(&g_ee[kbase + tid]);

    CP_WAIT(0);
    __syncthreads();

    // ---- load A fragments into registers
    u32 afr[2][4][4];
    {
        int g = lane >> 3;
        int arow = wrow + (g & 1) * 8 + (lane & 7);
        int acol = (g >> 1) * 16;
#pragma unroll
        for (int t = 0; t < 2; t++)
#pragma unroll
            for (int kt = 0; kt < 4; kt++) {
                u32 addr = smb + A_OFF + t * 16384 +
                           SW128((u32)(arow * 128 + kt * 32 + acol));
                LDSM_X4(afr[t][kt], addr);
            }
    }

    float best0 = 3.4e38f, best1 = 3.4e38f;
    u32   idx0 = 0, idx1 = 0;

    const int brow    = lane & 7;
    const int bcolsel = ((lane >> 3) & 1) * 16;
    const int btile   = (lane >> 4) * 8;

    for (int c = 0; c < NCHUNK; c++) {
        const u32 bufc = smb + B_OFF + (u32)(c & 1) * 32768;

        __syncthreads();
        if (c < NCHUNK - 1) {
            int cn = c + 1;
            u32 bufn = smb + B_OFF + (u32)(cn & 1) * 32768;
#pragma unroll
            for (int u = tid; u < 2048; u += NTHR) {
                int term = u >> 10;
                int rem  = u & 1023;
                int krow = rem >> 3;
                int seg  = rem & 7;
                const uint4* src = &g_esplit[term][(size_t)(kbase + cn * NCK + krow) * 8 + seg];
                u32 dst = bufn + term * 16384 + SW128((u32)(krow * 128 + seg * 16));
                CP_ASYNC16(dst, src);
            }
            CP_COMMIT();
            CP_WAIT(1);
        } else {
            CP_WAIT(0);
        }
        __syncthreads();

        for (int p = 0; p < 8; p++) {        // n-tile pairs
            float ccA0[4] = {0, 0, 0, 0}, ccA1[4] = {0, 0, 0, 0};
            float ccB0[4] = {0, 0, 0, 0}, ccB1[4] = {0, 0, 0, 0};
            int rbase = (p * 16 + btile + brow) * 128 + bcolsel;

#pragma unroll
            for (int h = 0; h < 2; h++) {
                u32 bb[2][2][4];
#pragma unroll
                for (int t = 0; t < 2; t++)
#pragma unroll
                    for (int q = 0; q < 2; q++) {
                        int kt = h * 2 + q;
                        u32 addr = bufc + t * 16384 + SW128((u32)(rbase + kt * 32));
                        LDSM_X4(bb[t][q], addr);
                    }
#pragma unroll
                for (int q = 0; q < 2; q++) {
                    int kt = h * 2 + q;
                    MMA_F16(ccA0, afr[0][kt], bb[1][q][0], bb[1][q][1]);
                    MMA_F16(ccB0, afr[0][kt], bb[1][q][2], bb[1][q][3]);
                    MMA_F16(ccA1, afr[1][kt], bb[0][q][0], bb[0][q][1]);
                    MMA_F16(ccB1, afr[1][kt], bb[0][q][2], bb[0][q][3]);
                    MMA_F16(ccA0, afr[0][kt], bb[0][q][0], bb[0][q][1]);
                    MMA_F16(ccB0, afr[0][kt], bb[0][q][2], bb[0][q][3]);
                }
            }

            int kl = c * NCK + p * 16 + 2 * (lane & 3);
            u32 kcA = (u32)(kbase + kl);
            u32 kcB = kcA + 8;
            float eA0 = ees[kl],     eA1 = ees[kl + 1];
            float eB0 = ees[kl + 8], eB1 = ees[kl + 9];
            {
                float d0 = fmaf(-2.0f, ccA0[0] + ccA1[0], eA0);
                float d1 = fmaf(-2.0f, ccA0[1] + ccA1[1], eA1);
                float cv = (d1 < d0) ? d1 : d0;
                u32   ck = (d1 < d0) ? kcA + 1 : kcA;
                if (cv < best0) { best0 = cv; idx0 = ck; }
                float d2 = fmaf(-2.0f, ccA0[2] + ccA1[2], eA0);
                float d3 = fmaf(-2.0f, ccA0[3] + ccA1[3], eA1);
                float cw = (d3 < d2) ? d3 : d2;
                u32   cx = (d3 < d2) ? kcA + 1 : kcA;
                if (cw < best1) { best1 = cw; idx1 = cx; }
            }
            {
                float d0 = fmaf(-2.0f, ccB0[0] + ccB1[0], eB0);
                float d1 = fmaf(-2.0f, ccB0[1] + ccB1[1], eB1);
                float cv = (d1 < d0) ? d1 : d0;
                u32   ck = (d1 < d0) ? kcB + 1 : kcB;
                if (cv < best0) { best0 = cv; idx0 = ck; }
                float d2 = fmaf(-2.0f, ccB0[2] + ccB1[2], eB0);
                float d3 = fmaf(-2.0f, ccB0[3] + ccB1[3], eB1);
                float cw = (d3 < d2) ? d3 : d2;
                u32   cx = (d3 < d2) ? kcB + 1 : kcB;
                if (cw < best1) { best1 = cw; idx1 = cx; }
            }
        }
    }

    // ---- reduce argmin across lanes, publish to global keys
    u64 key0 = pack_key(best0, idx0);
    u64 key1 = pack_key(best1, idx1);
#pragma unroll
    for (int o = 1; o <= 2; o <<= 1) {
        u64 t0 = __shfl_xor_sync(0xFFFFFFFFu, key0, o);
        u64 t1 = __shfl_xor_sync(0xFFFFFFFFu, key1, o);
        if (t0 < key0) key0 = t0;
        if (t1 < key1) key1 = t1;
    }
    if ((lane & 3) == 0) {
        int r0 = wrow + (lane >> 2);
        atomicMin(&g_key[row0 + r0],     key0);
        atomicMin(&g_key[row0 + r0 + 8], key1);
    }
    __threadfence();
    __syncthreads();
    if (tid == 0) {
        int old = atomicAdd(&g_cnt[tile], 1);
        *flagp = (old == NSLICE - 1) ? 1 : 0;
    }
    __syncthreads();
    if (*flagp == 0) return;

    // ================= last block of this tile: fused epilogue ==============
    __threadfence();

    if (tid < BM) {
        u64 k;
        asm volatile("ld.global.cg.u64 %0, [%1];" : "=l"(k) : "l"(&g_key[row0 + tid]));
        int idx = (int)(k & 0xFFFFFFFFull);
        sidx[tid] = idx;
        out[O_IDX + row0 + tid] = (float)idx;
        atomicAdd(&g_ni[idx], 1.0f);
    }
    __syncthreads();

    float lacc = 0.0f;
    for (int i = tid; i < BM * 32; i += NTHR) {
        int d2 = i >> 7;
        int m  = i & 127;
        u32 sw = SW128((u32)(m * 128 + d2 * 4));
        u32 w0 = *reinterpret_cast<u32*>(sm + A_OFF + sw);
        u32 w1 = *reinterpret_cast<u32*>(sm + A_OFF + 16384 + sw);
        float zlo = hf_lo(w0) + hf_lo(w1);
        float zhi = hf_hi(w0) + hf_hi(w1);
        int idx = sidx[m];
        int d = d2 * 2;
        float2 q = __ldg(reinterpret_cast<const float2*>(emb + (size_t)idx * DIM + d));
        float dlo = q.x - zlo, dhi = q.y - zhi;
        lacc += dlo * dlo + dhi * dhi;
        int row = row0 + m;
        int b = row >> 10, hw = row & 1023;
        size_t obase = ((size_t)(b * DIM + d) << 10) + hw;
        out[O_QV + obase]        = zlo + dlo;
        out[O_QV + obase + 1024] = zhi + dhi;
        atomicAdd(&g_dw[idx * DIM + d],     zlo);
        atomicAdd(&g_dw[idx * DIM + d + 1], zhi);
    }
#pragma unroll
    for (int o = 16; o > 0; o >>= 1) lacc += __shfl_xor_sync(0xFFFFFFFFu, lacc, o);
    if (lane == 0) lred[wid] = lacc;
    __syncthreads();
    if (tid == 0) {
        float s = 0.0f;
#pragma unroll
        for (int w = 0; w < NTHR / 32; w++) s += lred[w];
        atomicAdd(&g_loss, s);
    }
}

// ---------------------------------------------------------------------------
// Kernel 2: smoothing + EMA + new embeddings
// ---------------------------------------------------------------------------
__global__ __launch_bounds__(256)
void k_final(const float* __restrict__ cs, const float* __restrict__ ema,
             float* __restrict__ out) {
    __shared__ float red[8];
    const int tid = threadIdx.x;

    float part = 0.0f;
#pragma unroll
    for (int k = tid; k < KCODES; k += 256)
        part += cs[k] * 0.99f + g_ni[k] * 0.01f;
#pragma unroll
    for (int o = 16; o > 0; o >>= 1) part += __shfl_xor_sync(0xFFFFFFFFu, part, o);
    if ((tid & 31) == 0) red[tid >> 5] = part;
    __syncthreads();
    float n = 0.0f;
#pragma unroll
    for (int w = 0; w < 8; w++) n += red[w];

    if (blockIdx.x == 0 && tid == 0)
        out[O_LOSS] = 0.25f * g_loss / 2097152.0f;

    const int i0 = (blockIdx.x * 256 + tid) * 4;
    const int k  = i0 >> 6;
    float raw = cs[k] * 0.99f + g_ni[k] * 0.01f;
    float smooth = (raw + 1e-5f) / (n + 1024.0f * 1e-5f) * n;
    if ((i0 & 63) == 0) out[O_CL + k] = smooth;

    float4 ev = *reinterpret_cast<const float4*>(ema + i0);
    float4 dv = *reinterpret_cast<const float4*>(g_dw + i0);
    float inv = 1.0f / smooth;
    float ne0 = ev.x * 0.99f + dv.x * 0.01f;
    float ne1 = ev.y * 0.99f + dv.y * 0.01f;
    float ne2 = ev.z * 0.99f + dv.z * 0.01f;
    float ne3 = ev.w * 0.99f + dv.w * 0.01f;
    out[O_EMA + i0 + 0] = ne0;  out[O_EMB + i0 + 0] = ne0 * inv;
    out[O_EMA + i0 + 1] = ne1;  out[O_EMB + i0 + 1] = ne1 * inv;
    out[O_EMA + i0 + 2] = ne2;  out[O_EMB + i0 + 2] = ne2 * inv;
    out[O_EMA + i0 + 3] = ne3;  out[O_EMB + i0 + 3] = ne3 * inv;
}

// ---------------------------------------------------------------------------
extern "C" void kernel_launch(void* const* d_in, const int* in_sizes, int n_in,
                              void* d_out, int out_size) {
    const float* z   = (const float*)d_in[0];
    const float* emb = (const float*)d_in[1];
    const float* cs  = (const float*)d_in[2];
    const float* ema = (const float*)d_in[3];
    float* out = (float*)d_out;

    static bool attr_set = false;
    if (!attr_set) {
        cudaFuncSetAttribute(k_main, cudaFuncAttributeMaxDynamicSharedMemorySize, SMEM_SZ);
        attr_set = true;
    }

    k_prep<<<128, 256>>>(emb, z);
    k_main<<<(N_TOT / BM) * NSLICE, NTHR, SMEM_SZ>>>(emb, out);
    k_final<<<64, 256>>>(cs, ema, out);
}

// round 14
// speedup vs baseline: 1.7614x; 1.7003x over previous
#include <cuda_runtime.h>
#include <cuda_fp16.h>
#include <cstdint>

#define N_TOT  32768
#define DIM    64
#define KCODES 1024
#define BM     128
#define NTHR   256
#define NCHUNK 8      // 1024 codes / 128 per chunk
#define NCK    128

// mixed-size grid: blocks 0..147 -> 128 rows; 148..291 -> 96 rows; 292..295 idle
#define NB1    148
#define ROWS1  128
#define NB2    144
#define ROWS2  96
#define GRID   296

// output offsets (float32 elements), concatenated in reference return order
#define O_QV   0
#define O_IDX  2097152
#define O_LOSS 2129920
#define O_EMB  2129921     // ODD offset -> scalar stores only
#define O_CL   2195457
#define O_EMA  2196481     // ODD offset -> scalar stores only

typedef unsigned long long u64;
typedef unsigned int u32;

// ---- scratch (__device__ globals; no allocations allowed) ----
__device__ float g_dw[KCODES * DIM];
__device__ float g_ni[KCODES];
__device__ float g_ee[KCODES];
__device__ float g_loss;
__device__ uint4 g_esplit[2][KCODES * 8];   // 2 fp16 split terms, [1024 codes][128B rows]

// ---- smem layout (dynamic, 102400 B -> 2 blocks/SM) ----
#define A_OFF    0          // 2 x 16KB fp16 A tiles (SW128), z split
#define B_OFF    32768      // 2 x (2 x 16KB) fp16 B tiles (double buffered)
#define EE_OFF   98304      // 1024 floats ||e||^2
#define SMEM_SZ  102400

#define SW128(b) ((b) ^ (((b) >> 3) & 0x70))

__device__ __forceinline__ u32 smem_u32(const void* p) {
    u32 a;
    asm("{ .reg .u64 t; cvta.to.shared.u64 t, %1; cvt.u32.u64 %0, t; }" : "=r"(a) : "l"(p));
    return a;
}
#define LDSM_X4(r, addr) \
    asm volatile("ldmatrix.sync.aligned.m8n8.x4.shared.b16 {%0,%1,%2,%3}, [%4];" \
        : "=r"((r)[0]), "=r"((r)[1]), "=r"((r)[2]), "=r"((r)[3]) : "r"(addr))
#define MMA_F16(c, a, b0, b1) \
    asm volatile("mma.sync.aligned.m16n8k16.row.col.f32.f16.f16.f32 " \
        "{%0,%1,%2,%3}, {%4,%5,%6,%7}, {%8,%9}, {%0,%1,%2,%3};" \
        : "+f"((c)[0]), "+f"((c)[1]), "+f"((c)[2]), "+f"((c)[3]) \
        : "r"((a)[0]), "r"((a)[1]), "r"((a)[2]), "r"((a)[3]), \
          "r"(b0), "r"(b1))
#define CP_ASYNC16(dst, src) \
    asm volatile("cp.async.cg.shared.global [%0], [%1], 16;" :: "r"(dst), "l"(src))
#define CP_COMMIT() asm volatile("cp.async.commit_group;" ::: "memory")
#define CP_WAIT(n)  asm volatile("cp.async.wait_group %0;" :: "n"(n) : "memory")

// 2-way fp16 split: x ~= h0 + h1, residual ~2^-22 |x|
__device__ __forceinline__ void split2(float x, u32& h0, u32& h1) {
    __half a = __float2half_rn(x);
    float f0 = __half2float(a);
    __half b = __float2half_rn(x - f0);
    h0 = (u32)__half_as_ushort(a);
    h1 = (u32)__half_as_ushort(b);
}
__device__ __forceinline__ float hf_lo(u32 w) {
    return __half2float(__ushort_as_half((unsigned short)(w & 0xffffu)));
}
__device__ __forceinline__ float hf_hi(u32 w) {
    return __half2float(__ushort_as_half((unsigned short)(w >> 16)));
}
__device__ __forceinline__ u64 pack_key(float v, u32 k) {
    u32 u = __float_as_uint(v);
    u = (u & 0x80000000u) ? ~u : (u | 0x80000000u);
    return ((u64)u << 32) | (u64)k;
}

// ---------------------------------------------------------------------------
// Kernel 0: zero scratch, ||e||^2, split embeddings into 2 fp16 arrays
// ---------------------------------------------------------------------------
__global__ void k_prep(const float* __restrict__ emb) {
    int t = blockIdx.x * blockDim.x + threadIdx.x;   // 16384 threads
    reinterpret_cast<float4*>(g_dw)[t] = make_float4(0.f, 0.f, 0.f, 0.f);
    {
        int code = t >> 4, dq = t & 15;
        float4 v = __ldg(reinterpret_cast<const float4*>(emb) + t);
        u32 h0[4], h1[4];
        split2(v.x, h0[0], h1[0]);
        split2(v.y, h0[1], h1[1]);
        split2(v.z, h0[2], h1[2]);
        split2(v.w, h0[3], h1[3]);
        u32 base = code * 32 + dq * 2;
        u32* p0 = reinterpret_cast<u32*>(g_esplit[0]);
        u32* p1 = reinterpret_cast<u32*>(g_esplit[1]);
        p0[base] = h0[0] | (h0[1] << 16);  p0[base + 1] = h0[2] | (h0[3] << 16);
        p1[base] = h1[0] | (h1[1] << 16);  p1[base + 1] = h1[2] | (h1[3] << 16);
    }
    if (t < KCODES) {
        g_ni[t] = 0.0f;
        const float4* e4 = reinterpret_cast<const float4*>(emb + (size_t)t * DIM);
        float s = 0.0f;
#pragma unroll
        for (int i = 0; i < 16; i++) {
            float4 v = e4[i];
            s += v.x * v.x + v.y * v.y + v.z * v.z + v.w * v.w;
        }
        g_ee[t] = s;
    }
    if (t == 0) g_loss = 0.0f;
}

// ---------------------------------------------------------------------------
// Kernel 1: HMMA distances (3-term fp16 split), cp.async double-buffered B.
// Mixed-size tiles: 128-row and 96-row blocks paired per SM via bid%148 LUT.
// ---------------------------------------------------------------------------
__global__ __launch_bounds__(NTHR, 2)
void k_main(const float* __restrict__ z, const float* __restrict__ emb,
            float* __restrict__ out) {
    extern __shared__ __align__(16) unsigned char sm[];
    int*   sidx = reinterpret_cast<int*>(sm + B_OFF);     // alias B (post-loop)
    float* lred = reinterpret_cast<float*>(sm + B_OFF + 2048);
    float* ees  = reinterpret_cast<float*>(sm + EE_OFF);

    const int bid = blockIdx.x;
    int row0, bmloc;
    if (bid < NB1)                { row0 = bid * ROWS1;                    bmloc = ROWS1; }
    else if (bid < NB1 + NB2)     { row0 = NB1 * ROWS1 + (bid - NB1) * ROWS2; bmloc = ROWS2; }
    else                          return;   // padding blocks

    const u32 smb = smem_u32(sm);
    const int tid  = threadIdx.x;
    const int lane = tid & 31;
    const int wid  = tid >> 5;
    const int wrow = wid * 16;
    const bool live = (wrow < bmloc);        // warp owns real rows?

    // ---- stage ||e||^2 into smem
    for (int i = tid; i < KCODES; i += NTHR) ees[i] = __ldg(&g_ee[i]);

    // ---- prefetch chunk 0 B into buffer 0 (cp.async)
#pragma unroll
    for (int u = tid; u < 2048; u += NTHR) {
        int term = u >> 10;
        int rem  = u & 1023;
        int krow = rem >> 3;
        int seg  = rem & 7;
        const uint4* src = &g_esplit[term][(size_t)krow * 8 + seg];
        u32 dst = smb + B_OFF + term * 16384 + SW128((u32)(krow * 128 + seg * 16));
        CP_ASYNC16(dst, src);
    }
    CP_COMMIT();

    // ---- build 2 fp16 A tiles from z (only bmloc rows)
    for (int i = tid; i < bmloc * 16; i += NTHR) {
        int m = i >> 4, dq = i & 15;
        float4 v = *reinterpret_cast<const float4*>(z + (size_t)(row0 + m) * DIM + dq * 4);
        u32 h0[4], h1[4];
        split2(v.x, h0[0], h1[0]);
        split2(v.y, h0[1], h1[1]);
        split2(v.z, h0[2], h1[2]);
        split2(v.w, h0[3], h1[3]);
        u32 sw = SW128((u32)(m * 128 + dq * 8));
        u32* d0 = reinterpret_cast<u32*>(sm + A_OFF + sw);
        u32* d1 = reinterpret_cast<u32*>(sm + A_OFF + 16384 + sw);
        d0[0] = h0[0] | (h0[1] << 16);  d0[1] = h0[2] | (h0[3] << 16);
        d1[0] = h1[0] | (h1[1] << 16);  d1[1] = h1[2] | (h1[3] << 16);
    }
    __syncthreads();

    // ---- load A fragments into registers (dead warps load stale smem; unused)
    u32 afr[2][4][4];
    {
        int g = lane >> 3;
        int arow = (live ? wrow : 0) + (g & 1) * 8 + (lane & 7);
        int acol = (g >> 1) * 16;
#pragma unroll
        for (int t = 0; t < 2; t++)
#pragma unroll
            for (int kt = 0; kt < 4; kt++) {
                u32 addr = smb + A_OFF + t * 16384 +
                           SW128((u32)(arow * 128 + kt * 32 + acol));
                LDSM_X4(afr[t][kt], addr);
            }
    }

    float best0 = 3.4e38f, best1 = 3.4e38f;
    u32   idx0 = 0, idx1 = 0;

    const int brow    = lane & 7;
    const int bcolsel = ((lane >> 3) & 1) * 16;
    const int btile   = (lane >> 4) * 8;

    for (int c = 0; c < NCHUNK; c++) {
        const u32 bufc = smb + B_OFF + (u32)(c & 1) * 32768;

        __syncthreads();   // protect buffer (c+1)&1 from stragglers in chunk c-1
        if (c < NCHUNK - 1) {
            int cn = c + 1;
            u32 bufn = smb + B_OFF + (u32)(cn & 1) * 32768;
#pragma unroll
            for (int u = tid; u < 2048; u += NTHR) {
                int term = u >> 10;
                int rem  = u & 1023;
                int krow = rem >> 3;
                int seg  = rem & 7;
                const uint4* src = &g_esplit[term][(size_t)(cn * NCK + krow) * 8 + seg];
                u32 dst = bufn + term * 16384 + SW128((u32)(krow * 128 + seg * 16));
                CP_ASYNC16(dst, src);
            }
            CP_COMMIT();
            CP_WAIT(1);
        } else {
            CP_WAIT(0);
        }
        __syncthreads();

        if (live) {
            for (int p = 0; p < 8; p++) {        // n-tile pairs: tiles 2p, 2p+1
                float ccA0[4] = {0, 0, 0, 0}, ccA1[4] = {0, 0, 0, 0};
                float ccB0[4] = {0, 0, 0, 0}, ccB1[4] = {0, 0, 0, 0};
                int rbase = (p * 16 + btile + brow) * 128 + bcolsel;

#pragma unroll
                for (int h = 0; h < 2; h++) {    // k-halves: kt {2h, 2h+1}
                    u32 bb[2][2][4];
#pragma unroll
                    for (int t = 0; t < 2; t++)
#pragma unroll
                        for (int q = 0; q < 2; q++) {
                            int kt = h * 2 + q;
                            u32 addr = bufc + t * 16384 + SW128((u32)(rbase + kt * 32));
                            LDSM_X4(bb[t][q], addr);
                        }
#pragma unroll
                    for (int q = 0; q < 2; q++) {
                        int kt = h * 2 + q;
                        MMA_F16(ccA0, afr[0][kt], bb[1][q][0], bb[1][q][1]);
                        MMA_F16(ccB0, afr[0][kt], bb[1][q][2], bb[1][q][3]);
                        MMA_F16(ccA1, afr[1][kt], bb[0][q][0], bb[0][q][1]);
                        MMA_F16(ccB1, afr[1][kt], bb[0][q][2], bb[0][q][3]);
                        MMA_F16(ccA0, afr[0][kt], bb[0][q][0], bb[0][q][1]);
                        MMA_F16(ccB0, afr[0][kt], bb[0][q][2], bb[0][q][3]);
                    }
                }

                u32 kcA = (u32)(c * NCK + p * 16 + 2 * (lane & 3));
                u32 kcB = kcA + 8;
                float eA0 = ees[kcA], eA1 = ees[kcA + 1];
                float eB0 = ees[kcB], eB1 = ees[kcB + 1];
                {
                    float d0 = fmaf(-2.0f, ccA0[0] + ccA1[0], eA0);
                    float d1 = fmaf(-2.0f, ccA0[1] + ccA1[1], eA1);
                    float cv = (d1 < d0) ? d1 : d0;
                    u32   ck = (d1 < d0) ? kcA + 1 : kcA;
                    if (cv < best0) { best0 = cv; idx0 = ck; }
                    float d2 = fmaf(-2.0f, ccA0[2] + ccA1[2], eA0);
                    float d3 = fmaf(-2.0f, ccA0[3] + ccA1[3], eA1);
                    float cw = (d3 < d2) ? d3 : d2;
                    u32   cx = (d3 < d2) ? kcA + 1 : kcA;
                    if (cw < best1) { best1 = cw; idx1 = cx; }
                }
                {
                    float d0 = fmaf(-2.0f, ccB0[0] + ccB1[0], eB0);
                    float d1 = fmaf(-2.0f, ccB0[1] + ccB1[1], eB1);
                    float cv = (d1 < d0) ? d1 : d0;
                    u32   ck = (d1 < d0) ? kcB + 1 : kcB;
                    if (cv < best0) { best0 = cv; idx0 = ck; }
                    float d2 = fmaf(-2.0f, ccB0[2] + ccB1[2], eB0);
                    float d3 = fmaf(-2.0f, ccB0[3] + ccB1[3], eB1);
                    float cw = (d3 < d2) ? d3 : d2;
                    u32   cx = (d3 < d2) ? kcB + 1 : kcB;
                    if (cw < best1) { best1 = cw; idx1 = cx; }
                }
            }
        }
    }

    // ---- reduce argmin across the 4 lanes sharing each row
    u64 key0 = pack_key(best0, idx0);
    u64 key1 = pack_key(best1, idx1);
#pragma unroll
    for (int o = 1; o <= 2; o <<= 1) {
        u64 t0 = __shfl_xor_sync(0xFFFFFFFFu, key0, o);
        u64 t1 = __shfl_xor_sync(0xFFFFFFFFu, key1, o);
        if (t0 < key0) key0 = t0;
        if (t1 < key1) key1 = t1;
    }
    __syncthreads();   // all mainloop B reads complete -> safe to alias
    if (live && (lane & 3) == 0) {
        int r0 = wrow + (lane >> 2);
        int i0 = (int)(key0 & 0xFFFFFFFFull);
        int i1 = (int)(key1 & 0xFFFFFFFFull);
        sidx[r0]     = i0;
        sidx[r0 + 8] = i1;
        out[O_IDX + row0 + r0]     = (float)i0;
        out[O_IDX + row0 + r0 + 8] = (float)i1;
        atomicAdd(&g_ni[i0], 1.0f);
        atomicAdd(&g_ni[i1], 1.0f);
    }
    __syncthreads();

    // ---- fused epilogue: reconstruct z from A tiles (z = h0+h1, ~2^-22 err)
    float lacc = 0.0f;
    for (int i = tid; i < bmloc * 32; i += NTHR) {   // (d-pair, m): m fast over bmloc
        int d2 = i / bmloc;       // 0..31 -> d = 2*d2
        int m  = i - d2 * bmloc;
        u32 sw = SW128((u32)(m * 128 + d2 * 4));
        u32 w0 = *reinterpret_cast<u32*>(sm + A_OFF + sw);
        u32 w1 = *reinterpret_cast<u32*>(sm + A_OFF + 16384 + sw);
        float zlo = hf_lo(w0) + hf_lo(w1);
        float zhi = hf_hi(w0) + hf_hi(w1);
        int idx = sidx[m];
        int d = d2 * 2;
        float2 q = __ldg(reinterpret_cast<const float2*>(emb + (size_t)idx * DIM + d));
        float dlo = q.x - zlo, dhi = q.y - zhi;
        lacc += dlo * dlo + dhi * dhi;
        int row = row0 + m;
        int b = row >> 10, hw = row & 1023;
        size_t obase = ((size_t)(b * DIM + d) << 10) + hw;
        out[O_QV + obase]        = zlo + dlo;
        out[O_QV + obase + 1024] = zhi + dhi;
        atomicAdd(&g_dw[idx * DIM + d],     zlo);
        atomicAdd(&g_dw[idx * DIM + d + 1], zhi);
    }
#pragma unroll
    for (int o = 16; o > 0; o >>= 1) lacc += __shfl_xor_sync(0xFFFFFFFFu, lacc, o);
    if (lane == 0) lred[wid] = lacc;
    __syncthreads();
    if (tid == 0) {
        float s = 0.0f;
#pragma unroll
        for (int w = 0; w < NTHR / 32; w++) s += lred[w];
        atomicAdd(&g_loss, s);
    }
}

// ---------------------------------------------------------------------------
// Kernel 2: smoothing + EMA + new embeddings
// ---------------------------------------------------------------------------
__global__ __launch_bounds__(256)
void k_final(const float* __restrict__ cs, const float* __restrict__ ema,
             float* __restrict__ out) {
    __shared__ float red[8];
    const int tid = threadIdx.x;

    float part = 0.0f;
#pragma unroll
    for (int k = tid; k < KCODES; k += 256)
        part += cs[k] * 0.99f + g_ni[k] * 0.01f;
#pragma unroll
    for (int o = 16; o > 0; o >>= 1) part += __shfl_xor_sync(0xFFFFFFFFu, part, o);
    if ((tid & 31) == 0) red[tid >> 5] = part;
    __syncthreads();
    float n = 0.0f;
#pragma unroll
    for (int w = 0; w < 8; w++) n += red[w];

    if (blockIdx.x == 0 && tid == 0)
        out[O_LOSS] = 0.25f * g_loss / 2097152.0f;

    const int i0 = (blockIdx.x * 256 + tid) * 4;
    const int k  = i0 >> 6;
    float raw = cs[k] * 0.99f + g_ni[k] * 0.01f;
    float smooth = (raw + 1e-5f) / (n + 1024.0f * 1e-5f) * n;
    if ((i0 & 63) == 0) out[O_CL + k] = smooth;

    float4 ev = *reinterpret_cast<const float4*>(ema + i0);
    float4 dv = *reinterpret_cast<const float4*>(g_dw + i0);
    float inv = 1.0f / smooth;
    float ne0 = ev.x * 0.99f + dv.x * 0.01f;
    float ne1 = ev.y * 0.99f + dv.y * 0.01f;
    float ne2 = ev.z * 0.99f + dv.z * 0.01f;
    float ne3 = ev.w * 0.99f + dv.w * 0.01f;
    out[O_EMA + i0 + 0] = ne0;  out[O_EMB + i0 + 0] = ne0 * inv;
    out[O_EMA + i0 + 1] = ne1;  out[O_EMB + i0 + 1] = ne1 * inv;
    out[O_EMA + i0 + 2] = ne2;  out[O_EMB + i0 + 2] = ne2 * inv;
    out[O_EMA + i0 + 3] = ne3;  out[O_EMB + i0 + 3] = ne3 * inv;
}

// ---------------------------------------------------------------------------
extern "C" void kernel_launch(void* const* d_in, const int* in_sizes, int n_in,
                              void* d_out, int out_size) {
    const float* z   = (const float*)d_in[0];
    const float* emb = (const float*)d_in[1];
    const float* cs  = (const float*)d_in[2];
    const float* ema = (const float*)d_in[3];
    float* out = (float*)d_out;

    static bool attr_set = false;
    if (!attr_set) {
        cudaFuncSetAttribute(k_main, cudaFuncAttributeMaxDynamicSharedMemorySize, SMEM_SZ);
        attr_set = true;
    }

    k_prep<<<64, 256>>>(emb);
    k_main<<<GRID, NTHR, SMEM_SZ>>>(z, emb, out);
    k_final<<<64, 256>>>(cs, ema, out);
}